// round 15
// baseline (speedup 1.0000x reference)
#include <cuda_runtime.h>
#include <cuda_bf16.h>

// Problem constants (fixed by the reference setup_inputs)
#define BATCH   16
#define HW      512
#define MCOMP   200000
#define NBLOCKS 1184           // 148 SMs * 8 blocks: one full resident wave
#define NTHR    256
#define PBMAX   160            // max blocks any batch can receive (worst case ~139)

#define EPS_F   1e-10f
#define THR_F   1.1f            // 1.0 + DELTA

// Dense per-batch partial layout: g_part[b*PBMAX + j]. Apportionment is a
// deterministic function of numComparisons, so the same slots are written on
// every graph replay; never-written slots stay zero (static init) forever.
__device__ float2 g_part[BATCH * PBMAX];

__device__ __forceinline__ void whdr_one(const float* __restrict__ img,
                                         const float2* __restrict__ c2,
                                         int m, float& ws, float& wm)
{
    const float2 p0 = c2[m * 3 + 0];   // (x1, y1)
    const float2 p1 = c2[m * 3 + 1];   // (x2, y2)
    const float2 p2 = c2[m * 3 + 2];   // (darker, weight)

    const int x1 = (int)p0.x, y1 = (int)p0.y;
    const int x2 = (int)p1.x, y2 = (int)p1.y;
    const int darker = (int)p2.x;
    const float w = p2.y;

    const float r1 = __ldg(img + y1 * HW + x1);
    const float r2 = __ldg(img + y2 * HW + x2);

    // alg = 1 if r2/(r1+eps) > thr ; 2 if r1/(r2+eps) > thr ; else 0
    // multiply-form (all values positive) avoids divides
    int alg = 0;
    if (r2 > THR_F * (r1 + EPS_F))      alg = 1;
    else if (r1 > THR_F * (r2 + EPS_F)) alg = 2;

    ws += w;
    if (alg != darker) wm += w;
}

// Deterministic largest-remainder apportionment of NBLOCKS blocks to BATCH
// batches, proportional to n_b. Fills S[b] (blocks per batch), Q[b] (prefix).
__device__ __forceinline__ void apportion_blocks(const int* __restrict__ n,
                                                 int* __restrict__ S,
                                                 int* __restrict__ Q)
{
    long long total = 0;
    #pragma unroll
    for (int i = 0; i < BATCH; i++) total += n[i];

    long long rem[BATCH];
    int used = 0;
    #pragma unroll
    for (int i = 0; i < BATCH; i++) {
        const long long num = (long long)NBLOCKS * n[i];
        S[i]   = (int)(num / total);
        rem[i] = num - (long long)S[i] * total;
        used  += S[i];
    }
    for (int extra = NBLOCKS - used; extra > 0; extra--) {
        int best = 0;
        long long bv = -1;
        #pragma unroll
        for (int i = 0; i < BATCH; i++) {
            if (rem[i] > bv) { bv = rem[i]; best = i; }
        }
        S[best]++;
        rem[best] = -2;   // consumed
    }
    int acc = 0;
    #pragma unroll
    for (int i = 0; i < BATCH; i++) { Q[i] = acc; acc += S[i]; }
}

// R13's proven mainloop, with blocks apportioned to batches proportional to
// n_b (balanced tails): each block takes a contiguous slice of its batch.
__global__ __launch_bounds__(NTHR, 8)
void whdr_partial_kernel(const float* __restrict__ v_input,
                         const float* __restrict__ comparisons,
                         const int*   __restrict__ numComparisons)
{
    __shared__ int s_n[BATCH];
    __shared__ int s_S[BATCH];
    __shared__ int s_Q[BATCH];

    const int tid  = threadIdx.x;
    const int lane = tid & 31;
    const int warp = tid >> 5;

    if (tid < BATCH) s_n[tid] = numComparisons[tid];
    __syncthreads();
    if (tid == 0) apportion_blocks(s_n, s_S, s_Q);
    __syncthreads();

    const int bid = blockIdx.x;
    int b = 0;
    #pragma unroll
    for (int i = 1; i < BATCH; i++) b += (bid >= s_Q[i]);

    const int Sb = s_S[b];
    const int j  = bid - s_Q[b];         // block index within batch b
    const int nb = s_n[b];

    const int lo = (int)(((long long)j       * nb) / Sb);
    const int hi = (int)(((long long)(j + 1) * nb) / Sb);

    const float* __restrict__ img = v_input + (size_t)b * HW * HW;
    const float2* __restrict__ c2 =
        (const float2*)(comparisons + (size_t)b * MCOMP * 6);

    float ws0 = 0.0f, wm0 = 0.0f;
    float ws1 = 0.0f, wm1 = 0.0f;

    // Identical loop body to the 28.7us record holder; only the index range
    // changed (contiguous balanced slice instead of per-batch grid-stride).
    int m = lo + tid;
    for (; m + NTHR < hi; m += 2 * NTHR) {
        whdr_one(img, c2, m,        ws0, wm0);
        whdr_one(img, c2, m + NTHR, ws1, wm1);
    }
    if (m < hi) whdr_one(img, c2, m, ws0, wm0);

    float ws = ws0 + ws1;
    float wm = wm0 + wm1;

    // block reduction (8 warps)
    __shared__ float s_ws[NTHR / 32];
    __shared__ float s_wm[NTHR / 32];
    #pragma unroll
    for (int o = 16; o > 0; o >>= 1) {
        ws += __shfl_down_sync(0xFFFFFFFFu, ws, o);
        wm += __shfl_down_sync(0xFFFFFFFFu, wm, o);
    }
    if (lane == 0) { s_ws[warp] = ws; s_wm[warp] = wm; }
    __syncthreads();
    if (warp == 0) {
        ws = (lane < NTHR / 32) ? s_ws[lane] : 0.0f;
        wm = (lane < NTHR / 32) ? s_wm[lane] : 0.0f;
        #pragma unroll
        for (int o = 4; o > 0; o >>= 1) {
            ws += __shfl_down_sync(0xFFFFFFFFu, ws, o);
            wm += __shfl_down_sync(0xFFFFFFFFu, wm, o);
        }
        if (lane == 0) g_part[b * PBMAX + j] = make_float2(ws, wm);
    }
}

// Final reduction with PDL (proven 0.6us win): dense fixed layout, 5 strided
// loads per lane, no branches.
__global__ __launch_bounds__(512)
void whdr_final_kernel(float* __restrict__ out)
{
#if __CUDA_ARCH__ >= 900
    cudaGridDependencySynchronize();
#endif

    const int warp = threadIdx.x >> 5;   // batch index, 0..15
    const int lane = threadIdx.x & 31;

    float ws = 0.0f, wm = 0.0f;
    #pragma unroll
    for (int k = 0; k < PBMAX / 32; k++) {
        const float2 p = g_part[warp * PBMAX + k * 32 + lane];
        ws += p.x;
        wm += p.y;
    }
    #pragma unroll
    for (int o = 16; o > 0; o >>= 1) {
        ws += __shfl_down_sync(0xFFFFFFFFu, ws, o);
        wm += __shfl_down_sync(0xFFFFFFFFu, wm, o);
    }

    __shared__ float s_per[BATCH];
    if (lane == 0) s_per[warp] = wm / ws;
    __syncthreads();

    if (threadIdx.x == 0) {
        float s = 0.0f;
        #pragma unroll
        for (int i = 0; i < BATCH; i++) s += s_per[i];
        out[0] = s * (1.0f / BATCH);
    }
}

extern "C" void kernel_launch(void* const* d_in, const int* in_sizes, int n_in,
                              void* d_out, int out_size)
{
    const float* v_input        = (const float*)d_in[0];
    const float* comparisons    = (const float*)d_in[1];
    const int*   numComparisons = (const int*)  d_in[2];
    float* out = (float*)d_out;

    whdr_partial_kernel<<<NBLOCKS, NTHR>>>(v_input, comparisons, numComparisons);

    // PDL launch of the final reduction (programmatic edge in the graph).
    cudaLaunchConfig_t cfg = {};
    cfg.gridDim  = dim3(1, 1, 1);
    cfg.blockDim = dim3(512, 1, 1);
    cfg.dynamicSmemBytes = 0;
    cfg.stream = 0;

    cudaLaunchAttribute attrs[1];
    attrs[0].id = cudaLaunchAttributeProgrammaticStreamSerialization;
    attrs[0].val.programmaticStreamSerializationAllowed = 1;
    cfg.attrs    = attrs;
    cfg.numAttrs = 1;

    cudaLaunchKernelEx(&cfg, whdr_final_kernel, out);
}

// round 17
// speedup vs baseline: 1.0708x; 1.0708x over previous
#include <cuda_runtime.h>
#include <cuda_bf16.h>

// Problem constants (fixed by the reference setup_inputs)
#define BATCH   16
#define HW      512
#define MCOMP   200000
#define NBLOCKS 1184           // 148 SMs * 8 blocks: one full resident wave
#define NTHR    256
#define PBMAX   160            // max blocks any batch can receive

#define EPS_F   1e-10f
#define THR_F   1.1f            // 1.0 + DELTA

// Dense per-batch partial layout: g_part[b*PBMAX + j]. Apportionment is a
// deterministic function of numComparisons, so the same slots are written on
// every graph replay; never-written slots stay zero (static init) forever.
__device__ float2 g_part[BATCH * PBMAX];

__device__ __forceinline__ void whdr_one(const float* __restrict__ img,
                                         const float2* __restrict__ c2,
                                         int m, float& ws, float& wm)
{
    const float2 p0 = c2[m * 3 + 0];   // (x1, y1)
    const float2 p1 = c2[m * 3 + 1];   // (x2, y2)
    const float2 p2 = c2[m * 3 + 2];   // (darker, weight)

    const int x1 = (int)p0.x, y1 = (int)p0.y;
    const int x2 = (int)p1.x, y2 = (int)p1.y;
    const int darker = (int)p2.x;
    const float w = p2.y;

    const float r1 = __ldg(img + y1 * HW + x1);
    const float r2 = __ldg(img + y2 * HW + x2);

    // alg = 1 if r2/(r1+eps) > thr ; 2 if r1/(r2+eps) > thr ; else 0
    // multiply-form (all values positive) avoids divides
    int alg = 0;
    if (r2 > THR_F * (r1 + EPS_F))      alg = 1;
    else if (r1 > THR_F * (r2 + EPS_F)) alg = 2;

    ws += w;
    if (alg != darker) wm += w;
}

// Balanced partial kernel: blocks apportioned to batches proportional to n_b
// via CHEAP fp64 arithmetic (ONE division total, no 64-bit integer division —
// the 16x ~500-cycle i64 divs in earlier rounds burned ~4-5us of prologue on
// every block). Each block processes a contiguous slice with the exact
// record-holding R2/R13 loop body.
__global__ __launch_bounds__(NTHR)
void whdr_partial_kernel(const float* __restrict__ v_input,
                         const float* __restrict__ comparisons,
                         const int*   __restrict__ numComparisons)
{
    __shared__ int    s_n[BATCH];
    __shared__ int    s_Q[BATCH + 1];    // block-count prefix per batch
    __shared__ double s_step[BATCH];     // records per block, per batch

    const int tid  = threadIdx.x;
    const int lane = tid & 31;
    const int warp = tid >> 5;

    if (tid < BATCH) s_n[tid] = numComparisons[tid];
    __syncthreads();

    if (tid == 0) {
        // prefix of n, then Q[i] = round-down of prefix * NBLOCKS/total.
        int pn[BATCH + 1];
        pn[0] = 0;
        #pragma unroll
        for (int i = 0; i < BATCH; i++) pn[i + 1] = pn[i] + s_n[i];
        const double inv = (double)NBLOCKS / (double)pn[BATCH];  // ONE division
        s_Q[0] = 0;
        #pragma unroll
        for (int i = 1; i < BATCH; i++) s_Q[i] = (int)((double)pn[i] * inv);
        s_Q[BATCH] = NBLOCKS;
    }
    __syncthreads();
    if (tid < BATCH) {
        // per-batch slice step, computed by 16 threads in parallel (1 div each)
        const int Sb = s_Q[tid + 1] - s_Q[tid];
        s_step[tid] = (double)s_n[tid] / (double)Sb;
    }
    __syncthreads();

    const int bid = blockIdx.x;
    int b = 0;
    #pragma unroll
    for (int i = 1; i < BATCH; i++) b += (bid >= s_Q[i]);

    const int    Sb   = s_Q[b + 1] - s_Q[b];
    const int    j    = bid - s_Q[b];       // block index within batch b
    const int    nb   = s_n[b];
    const double step = s_step[b];

    const int lo = (int)((double)j * step);
    const int hi = (j == Sb - 1) ? nb : (int)((double)(j + 1) * step);

    const float* __restrict__ img = v_input + (size_t)b * HW * HW;
    const float2* __restrict__ c2 =
        (const float2*)(comparisons + (size_t)b * MCOMP * 6);

    float ws0 = 0.0f, wm0 = 0.0f;
    float ws1 = 0.0f, wm1 = 0.0f;

    // Identical loop body to the 28.7us record holder.
    int m = lo + tid;
    for (; m + NTHR < hi; m += 2 * NTHR) {
        whdr_one(img, c2, m,        ws0, wm0);
        whdr_one(img, c2, m + NTHR, ws1, wm1);
    }
    if (m < hi) whdr_one(img, c2, m, ws0, wm0);

    float ws = ws0 + ws1;
    float wm = wm0 + wm1;

    // block reduction (8 warps)
    __shared__ float s_ws[NTHR / 32];
    __shared__ float s_wm[NTHR / 32];
    #pragma unroll
    for (int o = 16; o > 0; o >>= 1) {
        ws += __shfl_down_sync(0xFFFFFFFFu, ws, o);
        wm += __shfl_down_sync(0xFFFFFFFFu, wm, o);
    }
    if (lane == 0) { s_ws[warp] = ws; s_wm[warp] = wm; }
    __syncthreads();
    if (warp == 0) {
        ws = (lane < NTHR / 32) ? s_ws[lane] : 0.0f;
        wm = (lane < NTHR / 32) ? s_wm[lane] : 0.0f;
        #pragma unroll
        for (int o = 4; o > 0; o >>= 1) {
            ws += __shfl_down_sync(0xFFFFFFFFu, ws, o);
            wm += __shfl_down_sync(0xFFFFFFFFu, wm, o);
        }
        if (lane == 0) g_part[b * PBMAX + j] = make_float2(ws, wm);
    }
}

// Final reduction with PDL (proven 0.6us win): dense fixed layout, 5 strided
// loads per lane, no branches.
__global__ __launch_bounds__(512)
void whdr_final_kernel(float* __restrict__ out)
{
#if __CUDA_ARCH__ >= 900
    cudaGridDependencySynchronize();
#endif

    const int warp = threadIdx.x >> 5;   // batch index, 0..15
    const int lane = threadIdx.x & 31;

    float ws = 0.0f, wm = 0.0f;
    #pragma unroll
    for (int k = 0; k < PBMAX / 32; k++) {
        const float2 p = g_part[warp * PBMAX + k * 32 + lane];
        ws += p.x;
        wm += p.y;
    }
    #pragma unroll
    for (int o = 16; o > 0; o >>= 1) {
        ws += __shfl_down_sync(0xFFFFFFFFu, ws, o);
        wm += __shfl_down_sync(0xFFFFFFFFu, wm, o);
    }

    __shared__ float s_per[BATCH];
    if (lane == 0) s_per[warp] = wm / ws;
    __syncthreads();

    if (threadIdx.x == 0) {
        float s = 0.0f;
        #pragma unroll
        for (int i = 0; i < BATCH; i++) s += s_per[i];
        out[0] = s * (1.0f / BATCH);
    }
}

extern "C" void kernel_launch(void* const* d_in, const int* in_sizes, int n_in,
                              void* d_out, int out_size)
{
    const float* v_input        = (const float*)d_in[0];
    const float* comparisons    = (const float*)d_in[1];
    const int*   numComparisons = (const int*)  d_in[2];
    float* out = (float*)d_out;

    whdr_partial_kernel<<<NBLOCKS, NTHR>>>(v_input, comparisons, numComparisons);

    // PDL launch of the final reduction (programmatic edge in the graph).
    cudaLaunchConfig_t cfg = {};
    cfg.gridDim  = dim3(1, 1, 1);
    cfg.blockDim = dim3(512, 1, 1);
    cfg.dynamicSmemBytes = 0;
    cfg.stream = 0;

    cudaLaunchAttribute attrs[1];
    attrs[0].id = cudaLaunchAttributeProgrammaticStreamSerialization;
    attrs[0].val.programmaticStreamSerializationAllowed = 1;
    cfg.attrs    = attrs;
    cfg.numAttrs = 1;

    cudaLaunchKernelEx(&cfg, whdr_final_kernel, out);
}